// round 1
// baseline (speedup 1.0000x reference)
#include <cuda_runtime.h>
#include <math_constants.h>

// Problem constants (fixed by reference: B=4, S=1024, D=512, COMP=4)
#define BATCH   4
#define SEQ     1024
#define DIM     512
#define NCOMP   (SEQ / 4)          // 256
#define STEPS   (SEQ - NCOMP)      // 768
#define THREADS 512
#define NWARP   (THREADS / 32)     // 16

// Mutable working copy of x (input buffer must stay pristine across graph replays)
__device__ float g_x[BATCH * SEQ * DIM];

__global__ void copy_in_kernel(const float* __restrict__ in) {
    const float4* in4 = (const float4*)in;
    float4* out4 = (float4*)g_x;
    const int n4 = BATCH * SEQ * DIM / 4;
    for (int i = blockIdx.x * blockDim.x + threadIdx.x; i < n4;
         i += gridDim.x * blockDim.x)
        out4[i] = in4[i];
}

__global__ __launch_bounds__(THREADS)
void merge_kernel(float* __restrict__ out) {
    __shared__ float s_dot[SEQ];      // adjacent dot: s_dot[i] = <row i, row next[i]>
    __shared__ short s_nxt[SEQ];      // linked list (original indices), -1 = end
    __shared__ short s_prv[SEQ];
    __shared__ float s_redv[NWARP];
    __shared__ int   s_redi[NWARP];
    __shared__ float s_red2[2 * NWARP];
    __shared__ int   s_mid;
    __shared__ short s_order[NCOMP];

    const int tid  = threadIdx.x;
    const int lane = tid & 31;
    const int warp = tid >> 5;
    const int b    = blockIdx.x;
    float* x = g_x + (size_t)b * SEQ * DIM;

    // ---- init links ----
    for (int i = tid; i < SEQ; i += THREADS) {
        s_nxt[i] = (short)((i == SEQ - 1) ? -1 : i + 1);
        s_prv[i] = (short)(i - 1);
    }

    // ---- initial adjacent dots: warp w handles rows w, w+16, ... ----
    for (int j = warp; j < SEQ - 1; j += NWARP) {
        const float* a = x + (size_t)j * DIM;
        const float* c = a + DIM;
        float s = 0.f;
        #pragma unroll 4
        for (int d = lane; d < DIM; d += 32)
            s += a[d] * c[d];
        #pragma unroll
        for (int o = 16; o; o >>= 1)
            s += __shfl_down_sync(0xffffffffu, s, o);
        if (lane == 0) s_dot[j] = s;
    }
    if (tid == 0) s_dot[SEQ - 1] = -CUDART_INF_F;
    __syncthreads();

    // ---- 768 sequential merge steps ----
    for (int t = 0; t < STEPS; t++) {
        // argmax over s_dot (first-index tie-break to match jnp.argmax)
        float v0 = s_dot[tid];
        float v1 = s_dot[tid + THREADS];
        float bv; int bi;
        if (v1 > v0) { bv = v1; bi = tid + THREADS; } else { bv = v0; bi = tid; }
        #pragma unroll
        for (int o = 16; o; o >>= 1) {
            float ov = __shfl_down_sync(0xffffffffu, bv, o);
            int   oi = __shfl_down_sync(0xffffffffu, bi, o);
            if (ov > bv || (ov == bv && oi < bi)) { bv = ov; bi = oi; }
        }
        if (lane == 0) { s_redv[warp] = bv; s_redi[warp] = bi; }
        __syncthreads();
        if (warp == 0) {
            bv = (lane < NWARP) ? s_redv[lane] : -CUDART_INF_F;
            bi = (lane < NWARP) ? s_redi[lane] : 0x7fffffff;
            #pragma unroll
            for (int o = 8; o; o >>= 1) {
                float ov = __shfl_down_sync(0xffffffffu, bv, o);
                int   oi = __shfl_down_sync(0xffffffffu, bi, o);
                if (ov > bv || (ov == bv && oi < bi)) { bv = ov; bi = oi; }
            }
            if (lane == 0) s_mid = bi;
        }
        __syncthreads();

        const int mid  = s_mid;
        const int nxt  = s_nxt[mid];
        const int prev = s_prv[mid];
        const int nn   = s_nxt[nxt];

        // merged vector: avg of mid & nxt; store over mid's row
        float nv = 0.5f * (x[(size_t)mid * DIM + tid] + x[(size_t)nxt * DIM + tid]);
        x[(size_t)mid * DIM + tid] = nv;

        // the only two dots that change
        float p1 = (prev >= 0) ? x[(size_t)prev * DIM + tid] * nv : 0.f;
        float p2 = (nn   >= 0) ? nv * x[(size_t)nn  * DIM + tid] : 0.f;
        #pragma unroll
        for (int o = 16; o; o >>= 1) {
            p1 += __shfl_down_sync(0xffffffffu, p1, o);
            p2 += __shfl_down_sync(0xffffffffu, p2, o);
        }
        if (lane == 0) { s_red2[warp] = p1; s_red2[warp + NWARP] = p2; }
        __syncthreads();
        if (tid == 0) {
            float d1 = 0.f, d2 = 0.f;
            #pragma unroll
            for (int w = 0; w < NWARP; w++) { d1 += s_red2[w]; d2 += s_red2[w + NWARP]; }
            if (prev >= 0) s_dot[prev] = d1;
            s_dot[mid] = (nn >= 0) ? d2 : -CUDART_INF_F;
            s_dot[nxt] = -CUDART_INF_F;
            s_nxt[mid] = (short)nn;
            if (nn >= 0) s_prv[nn] = (short)mid;
        }
        __syncthreads();
    }

    // ---- gather first NCOMP surviving rows (head index 0 is never removed) ----
    if (tid == 0) {
        int idx = 0;
        for (int c = 0; c < NCOMP; c++) { s_order[c] = (short)idx; idx = s_nxt[idx]; }
    }
    __syncthreads();
    for (int r = 0; r < NCOMP; r++) {
        int src = s_order[r];
        out[((size_t)b * NCOMP + r) * DIM + tid] = x[(size_t)src * DIM + tid];
    }
}

extern "C" void kernel_launch(void* const* d_in, const int* in_sizes, int n_in,
                              void* d_out, int out_size) {
    const float* x = (const float*)d_in[0];
    float* out = (float*)d_out;
    copy_in_kernel<<<1024, 256>>>(x);
    merge_kernel<<<BATCH, THREADS>>>(out);
}

// round 2
// speedup vs baseline: 1.4045x; 1.4045x over previous
#include <cuda_runtime.h>
#include <math_constants.h>

// Problem constants (fixed by reference: B=4, S=1024, D=512, COMP=4)
#define BATCH   4
#define SEQ     1024
#define DIM     512
#define NCOMP   (SEQ / 4)          // 256
#define STEPS   (SEQ - NCOMP)      // 768

// Mutable working copy + scratch (no allocs allowed in kernel_launch)
__device__ float g_x[BATCH * SEQ * DIM];
__device__ float g_dot[BATCH * SEQ];
__device__ int   g_order[BATCH * NCOMP];

// ---------------- helpers ----------------
__device__ __forceinline__ unsigned f2ord(float f) {
    unsigned u = __float_as_uint(f);
    return (u >> 31) ? ~u : (u | 0x80000000u);
}
__device__ __forceinline__ float ord2f(unsigned m) {
    return __uint_as_float((m >> 31) ? (m & 0x7fffffffu) : ~m);
}

// ---------------- copy input to mutable scratch ----------------
__global__ void copy_in_kernel(const float* __restrict__ in) {
    const float4* in4 = (const float4*)in;
    float4* out4 = (float4*)g_x;
    const int n4 = BATCH * SEQ * DIM / 4;
    for (int i = blockIdx.x * blockDim.x + threadIdx.x; i < n4;
         i += gridDim.x * blockDim.x)
        out4[i] = in4[i];
}

// ---------------- initial adjacent dots (one warp per dot, parallel) ----------------
__global__ void init_dots_kernel(const float* __restrict__ in) {
    int w = (blockIdx.x * blockDim.x + threadIdx.x) >> 5;
    int lane = threadIdx.x & 31;
    if (w >= BATCH * SEQ) return;
    int b = w / SEQ, j = w % SEQ;
    float s;
    if (j == SEQ - 1) {
        s = -CUDART_INF_F;
    } else {
        const float4* a = (const float4*)(in + ((size_t)b * SEQ + j) * DIM);
        const float4* c = (const float4*)(in + ((size_t)b * SEQ + j + 1) * DIM);
        float acc = 0.f;
        #pragma unroll
        for (int k = 0; k < 4; k++) {
            float4 av = a[k * 32 + lane];
            float4 cv = c[k * 32 + lane];
            acc += av.x * cv.x + av.y * cv.y + av.z * cv.z + av.w * cv.w;
        }
        #pragma unroll
        for (int o = 16; o; o >>= 1) acc += __shfl_xor_sync(0xffffffffu, acc, o);
        s = acc;
    }
    if (lane == 0) g_dot[b * SEQ + j] = s;
}

// ---------------- single-warp merge state machine (one per sample) ----------------
__global__ __launch_bounds__(32)
void merge_kernel() {
    __shared__ float s_dot[SEQ];
    __shared__ short s_nxt[SEQ];
    __shared__ short s_prv[SEQ];

    const int lane = threadIdx.x;
    const int b = blockIdx.x;
    float* x = g_x + (size_t)b * SEQ * DIM;

    #pragma unroll
    for (int k = 0; k < SEQ / 32; k++) {
        int i = k * 32 + lane;
        s_dot[i] = g_dot[b * SEQ + i];
        s_nxt[i] = (short)((i == SEQ - 1) ? -1 : i + 1);
        s_prv[i] = (short)(i - 1);
    }
    __syncwarp();

    // full argmax over s_dot -> (value, first index). Lane handles entries k*32+lane.
    auto full_argmax = [&](float& obv, int& obi) {
        float v[4]; int ix[4];
        #pragma unroll
        for (int c = 0; c < 4; c++) { v[c] = -CUDART_INF_F; ix[c] = 0x7fffffff; }
        #pragma unroll
        for (int k = 0; k < 32; k++) {
            int e = k * 32 + lane;
            float d = s_dot[e];
            int c = k & 3;                    // index increases within each chain
            bool gt = d > v[c];
            v[c]  = gt ? d : v[c];
            ix[c] = gt ? e : ix[c];
        }
        float bv = v[0]; int bi = ix[0];
        #pragma unroll
        for (int c = 1; c < 4; c++) {
            bool rep = (v[c] > bv) || (v[c] == bv && ix[c] < bi);
            bv = rep ? v[c] : bv;
            bi = rep ? ix[c] : bi;
        }
        unsigned ord = f2ord(bv);
        unsigned m = __reduce_max_sync(0xffffffffu, ord);
        unsigned cand = (ord == m) ? (unsigned)bi : 0x7fffffffu;
        obi = (int)__reduce_min_sync(0xffffffffu, cand);
        obv = ord2f(m);
    };

    float bv; int mid;
    full_argmax(bv, mid);

    for (int t = 0; t < STEPS; t++) {
        const int nxt  = s_nxt[mid];     // broadcast reads (same addr, no conflict)
        const int prev = s_prv[mid];
        const int nn   = s_nxt[nxt];

        // poison dirty entries so the speculative scan can ignore them
        if (lane == 0) {
            s_dot[mid] = -CUDART_INF_F;
            s_dot[nxt] = -CUDART_INF_F;
            if (prev >= 0) s_dot[prev] = -CUDART_INF_F;
        }
        __syncwarp();

        // issue all row loads up front (lane owns dims c*128 + lane*4 .. +3)
        const float4* rm = (const float4*)(x + (size_t)mid * DIM);
        const float4* rn = (const float4*)(x + (size_t)nxt * DIM);
        const float4* rp = (prev >= 0) ? (const float4*)(x + (size_t)prev * DIM) : rm;
        const float4* rq = (nn   >= 0) ? (const float4*)(x + (size_t)nn   * DIM) : rm;
        float4 vm[4], vn[4], vp[4], vq[4];
        #pragma unroll
        for (int c = 0; c < 4; c++) {
            vm[c] = rm[c * 32 + lane];
            vn[c] = rn[c * 32 + lane];
            vp[c] = rp[c * 32 + lane];
            vq[c] = rq[c * 32 + lane];
        }

        // speculative argmax over the (poisoned) dot table, under the LDG shadow
        float sbv; int sbi;
        full_argmax(sbv, sbi);

        // merge: nv = 0.5*(mid+nxt); dots with neighbors
        float p1 = 0.f, p2 = 0.f;
        float4 nv[4];
        #pragma unroll
        for (int c = 0; c < 4; c++) {
            nv[c].x = 0.5f * (vm[c].x + vn[c].x);
            nv[c].y = 0.5f * (vm[c].y + vn[c].y);
            nv[c].z = 0.5f * (vm[c].z + vn[c].z);
            nv[c].w = 0.5f * (vm[c].w + vn[c].w);
            p1 += vp[c].x * nv[c].x + vp[c].y * nv[c].y + vp[c].z * nv[c].z + vp[c].w * nv[c].w;
            p2 += nv[c].x * vq[c].x + nv[c].y * vq[c].y + nv[c].z * vq[c].z + nv[c].w * vq[c].w;
        }
        float4* wrow = (float4*)(x + (size_t)mid * DIM);
        #pragma unroll
        for (int c = 0; c < 4; c++) wrow[c * 32 + lane] = nv[c];

        #pragma unroll
        for (int o = 16; o; o >>= 1) {
            p1 += __shfl_xor_sync(0xffffffffu, p1, o);
            p2 += __shfl_xor_sync(0xffffffffu, p2, o);
        }

        // commit new dots + links
        if (lane == 0) {
            if (prev >= 0) s_dot[prev] = p1;
            s_dot[mid] = (nn >= 0) ? p2 : -CUDART_INF_F;
            s_nxt[mid] = (short)nn;
            if (nn >= 0) s_prv[nn] = (short)mid;
        }
        __syncwarp();

        // next argmax = spec best vs the two refreshed entries (lex max on (v, -i))
        float cbv = sbv; int cbi = sbi;
        if (prev >= 0 && (p1 > cbv || (p1 == cbv && prev < cbi))) { cbv = p1; cbi = prev; }
        if (nn   >= 0 && (p2 > cbv || (p2 == cbv && mid  < cbi))) { cbv = p2; cbi = mid; }
        mid = cbi;
    }

    // survivor order (head 0 is never removed — removed rows are always 'nxt')
    if (lane == 0) {
        int idx = 0;
        for (int c = 0; c < NCOMP; c++) { g_order[b * NCOMP + c] = idx; idx = s_nxt[idx]; }
    }
}

// ---------------- gather survivors to output (parallel) ----------------
__global__ void gather_kernel(float* __restrict__ out) {
    int r = blockIdx.x;                 // 0 .. BATCH*NCOMP-1
    int b = r / NCOMP;
    int src = g_order[r];
    const float4* s = (const float4*)(g_x + ((size_t)b * SEQ + src) * DIM);
    float4* d = (float4*)(out + (size_t)r * DIM);
    d[threadIdx.x] = s[threadIdx.x];    // 128 threads x float4 = 512 floats
}

extern "C" void kernel_launch(void* const* d_in, const int* in_sizes, int n_in,
                              void* d_out, int out_size) {
    const float* x = (const float*)d_in[0];
    float* out = (float*)d_out;
    copy_in_kernel<<<256, 256>>>(x);
    init_dots_kernel<<<(BATCH * SEQ * 32) / 256, 256>>>(x);
    merge_kernel<<<BATCH, 32>>>();
    gather_kernel<<<BATCH * NCOMP, 128>>>(out);
}

// round 3
// speedup vs baseline: 1.8876x; 1.3440x over previous
#include <cuda_runtime.h>
#include <math_constants.h>

// Problem constants (fixed by reference: B=4, S=1024, D=512, COMP=4)
#define BATCH   4
#define SEQ     1024
#define DIM     512
#define NCOMP   (SEQ / 4)          // 256
#define STEPS   (SEQ - NCOMP)      // 768
#define NBLK    (SEQ / 32)         // 32 blocks of 32 dot entries

// Mutable working copy + scratch (no allocs allowed in kernel_launch)
__device__ float    g_x[BATCH * SEQ * DIM];
__device__ unsigned g_dotord[BATCH * SEQ];
__device__ int      g_order[BATCH * NCOMP];

// order-preserving float -> uint map (monotonic: a<b  <=>  f2ord(a)<f2ord(b))
__device__ __forceinline__ unsigned f2ord(float f) {
    unsigned u = __float_as_uint(f);
    return (u >> 31) ? ~u : (u | 0x80000000u);
}

// ---------------- copy input to mutable scratch ----------------
__global__ void copy_in_kernel(const float* __restrict__ in) {
    const float4* in4 = (const float4*)in;
    float4* out4 = (float4*)g_x;
    const int n4 = BATCH * SEQ * DIM / 4;
    for (int i = blockIdx.x * blockDim.x + threadIdx.x; i < n4;
         i += gridDim.x * blockDim.x)
        out4[i] = in4[i];
}

// ---------------- initial adjacent dots (one warp per dot, parallel) ----------------
__global__ void init_dots_kernel(const float* __restrict__ in) {
    int w = (blockIdx.x * blockDim.x + threadIdx.x) >> 5;
    int lane = threadIdx.x & 31;
    if (w >= BATCH * SEQ) return;
    int b = w / SEQ, j = w % SEQ;
    unsigned o;
    if (j == SEQ - 1) {
        o = 0u;  // absolute minimum in ord space
    } else {
        const float4* a = (const float4*)(in + ((size_t)b * SEQ + j) * DIM);
        const float4* c = (const float4*)(in + ((size_t)b * SEQ + j + 1) * DIM);
        float acc = 0.f;
        #pragma unroll
        for (int k = 0; k < 4; k++) {
            float4 av = a[k * 32 + lane];
            float4 cv = c[k * 32 + lane];
            acc += av.x * cv.x + av.y * cv.y + av.z * cv.z + av.w * cv.w;
        }
        #pragma unroll
        for (int of = 16; of; of >>= 1) acc += __shfl_xor_sync(0xffffffffu, acc, of);
        o = f2ord(acc);
    }
    if (lane == 0) g_dotord[b * SEQ + j] = o;
}

// ---------------- single-warp merge state machine (one per sample) ----------------
__global__ __launch_bounds__(32)
void merge_kernel() {
    __shared__ unsigned s_dotord[SEQ];   // adjacent dots, ord-mapped
    __shared__ short    s_nxt[SEQ];
    __shared__ short    s_prv[SEQ];
    __shared__ unsigned s_bm[NBLK];      // block maxima (ord)
    __shared__ int      s_bi[NBLK];      // block argmax (global entry index)

    const unsigned FULL = 0xffffffffu;
    const int lane = threadIdx.x;
    const int b = blockIdx.x;
    float* x = g_x + (size_t)b * SEQ * DIM;

    #pragma unroll
    for (int k = 0; k < SEQ / 32; k++) {
        int i = k * 32 + lane;
        s_dotord[i] = g_dotord[b * SEQ + i];
        s_nxt[i] = (short)((i == SEQ - 1) ? -1 : i + 1);
        s_prv[i] = (short)(i - 1);
    }
    __syncwarp();

    // build block maxima
    for (int blk = 0; blk < NBLK; blk++) {
        unsigned d = s_dotord[blk * 32 + lane];
        unsigned m = __reduce_max_sync(FULL, d);
        unsigned bal = __ballot_sync(FULL, d == m);
        if (lane == 0) { s_bm[blk] = m; s_bi[blk] = blk * 32 + __ffs(bal) - 1; }
    }
    __syncwarp();

    // initial global argmax
    int mid;
    {
        unsigned v = s_bm[lane];
        int vb = s_bi[lane];
        unsigned M = __reduce_max_sync(FULL, v);
        unsigned bal = __ballot_sync(FULL, v == M);
        int wl = __ffs(bal) - 1;
        mid = __shfl_sync(FULL, vb, wl);
    }

    int sb0 = 0, sb1 = 0, sb2 = 0;   // stale blocks (bm not yet refreshed)

    for (int t = 0; t < STEPS; t++) {
        const int nxt  = s_nxt[mid];
        const int prev = s_prv[mid];
        const int nn   = s_nxt[nxt];

        // ---- issue all row loads up front (L2-latency shadow) ----
        const float4* rm = (const float4*)(x + (size_t)mid * DIM);
        const float4* rn = (const float4*)(x + (size_t)nxt * DIM);
        const float4* rp = (prev >= 0) ? (const float4*)(x + (size_t)prev * DIM) : rm;
        const float4* rq = (nn   >= 0) ? (const float4*)(x + (size_t)nn   * DIM) : rm;
        float4 vm[4], vn[4], vp[4], vq[4];
        #pragma unroll
        for (int c = 0; c < 4; c++) {
            vm[c] = rm[c * 32 + lane];
            vn[c] = rn[c * 32 + lane];
            vp[c] = rp[c * 32 + lane];
            vq[c] = rq[c * 32 + lane];
        }

        // ---- (a) repair stale block maxima from last commit (under shadow) ----
        {
            unsigned d0 = s_dotord[sb0 * 32 + lane];
            unsigned m0 = __reduce_max_sync(FULL, d0);
            unsigned b0 = __ballot_sync(FULL, d0 == m0);
            unsigned d1 = s_dotord[sb1 * 32 + lane];
            unsigned m1 = __reduce_max_sync(FULL, d1);
            unsigned b1 = __ballot_sync(FULL, d1 == m1);
            unsigned d2 = s_dotord[sb2 * 32 + lane];
            unsigned m2 = __reduce_max_sync(FULL, d2);
            unsigned b2 = __ballot_sync(FULL, d2 == m2);
            if (lane == 0) {
                s_bm[sb0] = m0; s_bi[sb0] = sb0 * 32 + __ffs(b0) - 1;
                s_bm[sb1] = m1; s_bi[sb1] = sb1 * 32 + __ffs(b1) - 1;
                s_bm[sb2] = m2; s_bi[sb2] = sb2 * 32 + __ffs(b2) - 1;
            }
        }
        __syncwarp();

        // ---- (b) masked rescan of the blocks holding {prev, mid, nxt} ----
        const int dbp = (prev >= 0 ? prev : mid) >> 5;
        const int dbm = mid >> 5;
        const int dbn = nxt >> 5;
        unsigned mP, mM, mN; int iP, iM, iN;
        {
            int e = dbp * 32 + lane;
            unsigned d = s_dotord[e];
            if (e == prev || e == mid || e == nxt) d = 0u;
            mP = __reduce_max_sync(FULL, d);
            unsigned bal = __ballot_sync(FULL, d == mP);
            iP = dbp * 32 + __ffs(bal) - 1;
        }
        {
            int e = dbm * 32 + lane;
            unsigned d = s_dotord[e];
            if (e == prev || e == mid || e == nxt) d = 0u;
            mM = __reduce_max_sync(FULL, d);
            unsigned bal = __ballot_sync(FULL, d == mM);
            iM = dbm * 32 + __ffs(bal) - 1;
        }
        {
            int e = dbn * 32 + lane;
            unsigned d = s_dotord[e];
            if (e == prev || e == mid || e == nxt) d = 0u;
            mN = __reduce_max_sync(FULL, d);
            unsigned bal = __ballot_sync(FULL, d == mN);
            iN = dbn * 32 + __ffs(bal) - 1;
        }

        // ---- (c) scan block maxima, masking the dirty blocks ----
        unsigned sbv; int sbi;
        {
            unsigned v = s_bm[lane];
            int vb = s_bi[lane];
            if (lane == dbp || lane == dbm || lane == dbn) v = 0u;
            unsigned M = __reduce_max_sync(FULL, v);
            unsigned bal = __ballot_sync(FULL, v == M);
            int wl = __ffs(bal) - 1;
            sbi = __shfl_sync(FULL, vb, wl);
            sbv = M;
        }
        // fold in dirty-block candidates (lex order: value desc, index asc)
        if (mP > sbv || (mP == sbv && iP < sbi)) { sbv = mP; sbi = iP; }
        if (mM > sbv || (mM == sbv && iM < sbi)) { sbv = mM; sbi = iM; }
        if (mN > sbv || (mN == sbv && iN < sbi)) { sbv = mN; sbi = iN; }

        // ---- merge math (bitwise-identical expressions to the passing R2 kernel) ----
        float p1 = 0.f, p2 = 0.f;
        float4 nv[4];
        #pragma unroll
        for (int c = 0; c < 4; c++) {
            nv[c].x = 0.5f * (vm[c].x + vn[c].x);
            nv[c].y = 0.5f * (vm[c].y + vn[c].y);
            nv[c].z = 0.5f * (vm[c].z + vn[c].z);
            nv[c].w = 0.5f * (vm[c].w + vn[c].w);
            p1 += vp[c].x * nv[c].x + vp[c].y * nv[c].y + vp[c].z * nv[c].z + vp[c].w * nv[c].w;
            p2 += nv[c].x * vq[c].x + nv[c].y * vq[c].y + nv[c].z * vq[c].z + nv[c].w * vq[c].w;
        }
        float4* wrow = (float4*)(x + (size_t)mid * DIM);
        #pragma unroll
        for (int c = 0; c < 4; c++) wrow[c * 32 + lane] = nv[c];

        #pragma unroll
        for (int o = 16; o; o >>= 1) {
            p1 += __shfl_xor_sync(FULL, p1, o);
            p2 += __shfl_xor_sync(FULL, p2, o);
        }

        // ---- final selection: spec winner vs the two refreshed entries ----
        const unsigned p1o = f2ord(p1);
        const unsigned p2o = f2ord(p2);
        int newmid = sbi; unsigned newbv = sbv;
        if (prev >= 0 && (p1o > newbv || (p1o == newbv && prev < newmid))) { newbv = p1o; newmid = prev; }
        if (nn   >= 0 && (p2o > newbv || (p2o == newbv && mid  < newmid))) { newbv = p2o; newmid = mid; }

        // ---- commit table + links; mark blocks stale for next-step repair ----
        if (lane == 0) {
            if (prev >= 0) s_dotord[prev] = p1o;
            s_dotord[mid] = (nn >= 0) ? p2o : 0u;
            s_dotord[nxt] = 0u;
            s_nxt[mid] = (short)nn;
            if (nn >= 0) s_prv[nn] = (short)mid;
        }
        sb0 = dbp; sb1 = dbm; sb2 = dbn;
        __syncwarp();

        mid = newmid;
    }

    // survivor order (head 0 is never removed — removed rows are always 'nxt')
    if (lane == 0) {
        int idx = 0;
        for (int c = 0; c < NCOMP; c++) { g_order[b * NCOMP + c] = idx; idx = s_nxt[idx]; }
    }
}

// ---------------- gather survivors to output (parallel) ----------------
__global__ void gather_kernel(float* __restrict__ out) {
    int r = blockIdx.x;                 // 0 .. BATCH*NCOMP-1
    int b = r / NCOMP;
    int src = g_order[r];
    const float4* s = (const float4*)(g_x + ((size_t)b * SEQ + src) * DIM);
    float4* d = (float4*)(out + (size_t)r * DIM);
    d[threadIdx.x] = s[threadIdx.x];    // 128 threads x float4 = 512 floats
}

extern "C" void kernel_launch(void* const* d_in, const int* in_sizes, int n_in,
                              void* d_out, int out_size) {
    const float* x = (const float*)d_in[0];
    float* out = (float*)d_out;
    copy_in_kernel<<<256, 256>>>(x);
    init_dots_kernel<<<(BATCH * SEQ * 32) / 256, 256>>>(x);
    merge_kernel<<<BATCH, 32>>>();
    gather_kernel<<<BATCH * NCOMP, 128>>>(out);
}